// round 16
// baseline (speedup 1.0000x reference)
#include <cuda_runtime.h>
#include <cstddef>

#define BB 16
#define TT 512
#define DD 256
#define HH 4
#define HD 64
#define MM (BB*TT)          // 8192

// ---------------- scratch (static device memory; no allocs) ----------------
__device__ float g_q[MM*DD];
__device__ float g_k[MM*DD];
__device__ float g_v[MM*DD];
__device__ float g_oc[MM*DD];
__device__ float g_xp[TT*BB*16];             // per-step gate pre-activations
__device__ float g_hs[BB*TT*4];              // lstm hidden outputs
__device__ float g_Wc[16*256];               // folded gate@Wo weights
__device__ float g_bc[16];                   // folded bias (Wg.bo + b + theta)

__device__ __forceinline__ float ftanh(float x){
    float e = __expf(2.0f*x);
    return __fdividef(e - 1.0f, e + 1.0f);
}
// sigmoid for |z| <= 1 (Taylor-9, max err ~2e-6 at |z|=1), FMA-pipe only
__device__ __forceinline__ float sigd1(float z){
    float u = z*z;
    float p = -17.f/80640.f + u*(31.f/1451520.f);
    p = 1.f/480.f + u*p;
    p = -1.f/48.f + u*p;
    p = 0.25f + u*p;
    return 0.5f + z*p;
}
// tanh for |z| <= 1 (Pade(5,4) of continued fraction, max err ~5e-8)
__device__ __forceinline__ float tanh1(float z){
    float u = z*z;
    float num = 945.f + u*(105.f + u);
    float den = 945.f + u*(420.f + 15.f*u);
    return z*__fdividef(num, den);
}

__device__ __forceinline__ unsigned tf32u(float x){
    unsigned y; asm("cvt.rna.tf32.f32 %0, %1;" : "=r"(y) : "f"(x)); return y;
}
__device__ __forceinline__ float tf32f(float x){
    return __uint_as_float(tf32u(x));
}
__device__ __forceinline__ void mma_tf32(float&c0,float&c1,float&c2,float&c3,
    unsigned a0,unsigned a1,unsigned a2,unsigned a3,unsigned b0,unsigned b1){
    asm("mma.sync.aligned.m16n8k8.row.col.f32.tf32.tf32.f32 "
        "{%0,%1,%2,%3},{%4,%5,%6,%7},{%8,%9},{%0,%1,%2,%3};"
        : "+f"(c0),"+f"(c1),"+f"(c2),"+f"(c3)
        : "r"(a0),"r"(a1),"r"(a2),"r"(a3),"r"(b0),"r"(b1));
}

// ============================================================================
// Fold Wo into the gate weights: Wc[r][k] = sum_c Wgate_r[c] * Wo[c][k],
// bc[r] = sum_c Wgate_r[c]*bo[c] + b_r + theta_r.   Grid = 16 blocks (one per
// gate-row r), 256 threads (one per k). Wo column reads are warp-coalesced.
// ============================================================================
__global__ void wc_kernel(const float* __restrict__ Wf, const float* __restrict__ Wi,
                          const float* __restrict__ Wg, const float* __restrict__ Wo2,
                          const float* __restrict__ Wo, const float* __restrict__ bo,
                          const float* __restrict__ bf, const float* __restrict__ thf,
                          const float* __restrict__ bi, const float* __restrict__ thi,
                          const float* __restrict__ bg, const float* __restrict__ thg,
                          const float* __restrict__ bo2, const float* __restrict__ tho)
{
    __shared__ float sG[256];
    __shared__ float red[256];
    const int r = blockIdx.x;                 // 0..15
    const float* Wgate = (r<4)?Wf:(r<8)?Wi:(r<12)?Wg:Wo2;
    const float* bias  = (r<4)?bf:(r<8)?bi:(r<12)?bg:bo2;
    const float* th    = (r<4)?thf:(r<8)?thi:(r<12)?thg:tho;
    const int rr = r & 3;
    const int k = threadIdx.x;
    sG[k] = Wgate[rr*260 + k];
    __syncthreads();
    float acc = 0.f;
#pragma unroll 4
    for (int c=0; c<256; c++)
        acc += sG[c]*Wo[c*256 + k];
    g_Wc[r*256 + k] = acc;
    red[k] = sG[k]*bo[k];
    __syncthreads();
    for (int s=128; s>0; s>>=1){
        if (k < s) red[k] += red[k+s];
        __syncthreads();
    }
    if (k == 0) g_bc[r] = red[0] + bias[rr] + th[rr];
}

// ============================================================================
// Projection GEMM on tensor cores (tf32 mma.sync m16n8k8).
// C[M=8192, N=256] = A[M,256] @ W[N,256]^T + bias.  A = emb[idx[.]] gather.
// ============================================================================
#define AS 36
#define WS 36

__global__ __launch_bounds__(256, 2)
void proj_mma_kernel(const float* __restrict__ emb,
                     const int*   __restrict__ idx,
                     const float* __restrict__ Wq, const float* __restrict__ bq,
                     const float* __restrict__ Wk, const float* __restrict__ bk,
                     const float* __restrict__ Wv, const float* __restrict__ bv)
{
    __shared__ float sA[128*AS];
    __shared__ float sW[64*WS];
    const int sel = blockIdx.z;
    const float* Wm   = (sel==0)?Wq:(sel==1)?Wk:Wv;
    const float* bias = (sel==0)?bq:(sel==1)?bk:bv;
    float* C          = (sel==0)?g_q:(sel==1)?g_k:g_v;
    const int tid = threadIdx.x;
    const int bm = blockIdx.x*128, bn = blockIdx.y*64;
    const int w = tid>>5, lane = tid&31;
    const int g = lane>>2, t = lane&3;

    const int ar = tid>>1, ac0 = (tid&1)*16;        // A: row, 16 cols
    const int wr = tid>>2, wc0 = (tid&3)*8;         // W: row, 8 cols
    const float* arow = emb + (size_t)idx[bm+ar]*DD + ac0;
    const float* brow = Wm + (size_t)(bn+wr)*DD + wc0;

    float s[8][4] = {};
    const int qrow0 = (16*w + g)*AS;
    const int qrow1 = (16*w + g + 8)*AS;

#pragma unroll 1
    for (int kc=0; kc<8; kc++){
        __syncthreads();
#pragma unroll
        for (int j=0;j<16;j+=4){
            float4 v = *(const float4*)(arow + kc*32 + j);
            sA[ar*AS + ac0 + j + 0] = tf32f(v.x);
            sA[ar*AS + ac0 + j + 1] = tf32f(v.y);
            sA[ar*AS + ac0 + j + 2] = tf32f(v.z);
            sA[ar*AS + ac0 + j + 3] = tf32f(v.w);
        }
#pragma unroll
        for (int j=0;j<8;j+=4){
            float4 v = *(const float4*)(brow + kc*32 + j);
            sW[wr*WS + wc0 + j + 0] = tf32f(v.x);
            sW[wr*WS + wc0 + j + 1] = tf32f(v.y);
            sW[wr*WS + wc0 + j + 2] = tf32f(v.z);
            sW[wr*WS + wc0 + j + 3] = tf32f(v.w);
        }
        __syncthreads();

#pragma unroll
        for (int kk=0; kk<4; kk++){
            const int ko = kk*8 + t;
            unsigned a0 = *(const unsigned*)&sA[qrow0 + ko];
            unsigned a1 = *(const unsigned*)&sA[qrow1 + ko];
            unsigned a2 = *(const unsigned*)&sA[qrow0 + ko + 4];
            unsigned a3 = *(const unsigned*)&sA[qrow1 + ko + 4];
#pragma unroll
            for (int j=0;j<8;j++){
                unsigned b0 = *(const unsigned*)&sW[(8*j+g)*WS + ko];
                unsigned b1 = *(const unsigned*)&sW[(8*j+g)*WS + ko + 4];
                mma_tf32(s[j][0],s[j][1],s[j][2],s[j][3], a0,a1,a2,a3, b0,b1);
            }
        }
    }

    float* out0 = C + (size_t)(bm + 16*w + g)*DD + bn;
    float* out1 = C + (size_t)(bm + 16*w + g + 8)*DD + bn;
#pragma unroll
    for (int j=0;j<8;j++){
        int cb = 8*j + 2*t;
        float b0 = bias[bn + cb], b1 = bias[bn + cb + 1];
        float2 v0 = {s[j][0]+b0, s[j][1]+b1};
        float2 v1 = {s[j][2]+b0, s[j][3]+b1};
        *(float2*)(out0 + cb) = v0;
        *(float2*)(out1 + cb) = v1;
    }
}

// ============================================================================
// Fused flash attention on tensor cores (tf32 mma.sync m16n8k8).
// grid (4 m-chunks of 128 rows, 64 bh), 256 threads = 8 warps.
// ============================================================================
#define QS 68
#define KS 68
#define VS 72
#define PS 68
#define FLASH_SMEM ((128*QS + 64*KS + 64*VS + 128*PS)*4)

__global__ __launch_bounds__(256, 2)
void flash_kernel()
{
    extern __shared__ float sm[];
    float* sQ = sm;                 // [128][QS] tf32
    float* sK = sQ + 128*QS;        // [64][KS]  tf32 (n-major: sK[n][k])
    float* sV = sK + 64*KS;         // [64][VS]  tf32 (kv-major: sV[kv][d])
    float* sP = sV + 64*VS;         // [128][PS] tf32

    const int bh = blockIdx.y, b = bh>>2, h = bh&3;
    const int bm = blockIdx.x*128;
    const int tid = threadIdx.x;
    const int w = tid>>5, lane = tid&31;
    const int g = lane>>2, t = lane&3;

    {
        int r = tid>>1, d0 = (tid&1)*32;
        const float* src = g_q + ((size_t)(b*TT + bm + r))*DD + h*HD + d0;
#pragma unroll
        for (int j=0;j<32;j+=4){
            float4 v = *(const float4*)(src + j);
            sQ[r*QS + d0 + j + 0] = tf32f(v.x);
            sQ[r*QS + d0 + j + 1] = tf32f(v.y);
            sQ[r*QS + d0 + j + 2] = tf32f(v.z);
            sQ[r*QS + d0 + j + 3] = tf32f(v.w);
        }
    }

    float o[8][4] = {};
    float m0=-1e30f, m1=-1e30f, l0=0.f, l1=0.f;

    const int arow0 = (16*w + g)*PS;
    const int arow1 = (16*w + g + 8)*PS;
    const int qrow0 = (16*w + g)*QS;
    const int qrow1 = (16*w + g + 8)*QS;

    for (int n0=0; n0<TT; n0+=64){
        __syncthreads();
        {
            int n = tid>>2, d0 = (tid&3)*16;
            const float* ksrc = g_k + ((size_t)(b*TT + n0 + n))*DD + h*HD + d0;
            const float* vsrc = g_v + ((size_t)(b*TT + n0 + n))*DD + h*HD + d0;
#pragma unroll
            for (int j=0;j<16;j+=4){
                float4 kv4 = *(const float4*)(ksrc + j);
                float4 vv4 = *(const float4*)(vsrc + j);
                sK[n*KS + d0 + j + 0] = tf32f(kv4.x);
                sK[n*KS + d0 + j + 1] = tf32f(kv4.y);
                sK[n*KS + d0 + j + 2] = tf32f(kv4.z);
                sK[n*KS + d0 + j + 3] = tf32f(kv4.w);
                sV[n*VS + d0 + j + 0] = tf32f(vv4.x);
                sV[n*VS + d0 + j + 1] = tf32f(vv4.y);
                sV[n*VS + d0 + j + 2] = tf32f(vv4.z);
                sV[n*VS + d0 + j + 3] = tf32f(vv4.w);
            }
        }
        __syncthreads();

        float s[8][4] = {};
#pragma unroll
        for (int kk=0; kk<8; kk++){
            const int ko = kk*8 + t;
            unsigned a0 = *(const unsigned*)&sQ[qrow0 + ko];
            unsigned a1 = *(const unsigned*)&sQ[qrow1 + ko];
            unsigned a2 = *(const unsigned*)&sQ[qrow0 + ko + 4];
            unsigned a3 = *(const unsigned*)&sQ[qrow1 + ko + 4];
#pragma unroll
            for (int j=0;j<8;j++){
                unsigned b0 = *(const unsigned*)&sK[(8*j+g)*KS + ko];
                unsigned b1 = *(const unsigned*)&sK[(8*j+g)*KS + ko + 4];
                mma_tf32(s[j][0],s[j][1],s[j][2],s[j][3], a0,a1,a2,a3, b0,b1);
            }
        }

        float lm0=-1e30f, lm1=-1e30f;
#pragma unroll
        for (int j=0;j<8;j++){
            s[j][0]*=0.125f; s[j][1]*=0.125f; s[j][2]*=0.125f; s[j][3]*=0.125f;
            lm0 = fmaxf(lm0, fmaxf(s[j][0], s[j][1]));
            lm1 = fmaxf(lm1, fmaxf(s[j][2], s[j][3]));
        }
        lm0 = fmaxf(lm0, __shfl_xor_sync(0xffffffffu, lm0, 1));
        lm0 = fmaxf(lm0, __shfl_xor_sync(0xffffffffu, lm0, 2));
        lm1 = fmaxf(lm1, __shfl_xor_sync(0xffffffffu, lm1, 1));
        lm1 = fmaxf(lm1, __shfl_xor_sync(0xffffffffu, lm1, 2));
        float nm0 = fmaxf(m0, lm0), nm1 = fmaxf(m1, lm1);
        float c0 = __expf(m0 - nm0), c1 = __expf(m1 - nm1);
        m0 = nm0; m1 = nm1;
        float ls0 = 0.f, ls1 = 0.f;
#pragma unroll
        for (int j=0;j<8;j++){
            float p00 = __expf(s[j][0]-nm0), p01 = __expf(s[j][1]-nm0);
            float p10 = __expf(s[j][2]-nm1), p11 = __expf(s[j][3]-nm1);
            ls0 += p00 + p01;  ls1 += p10 + p11;
            int cb = 8*j + 2*t;
            sP[arow0 + cb]     = tf32f(p00);
            sP[arow0 + cb + 1] = tf32f(p01);
            sP[arow1 + cb]     = tf32f(p10);
            sP[arow1 + cb + 1] = tf32f(p11);
        }
        ls0 += __shfl_xor_sync(0xffffffffu, ls0, 1);
        ls0 += __shfl_xor_sync(0xffffffffu, ls0, 2);
        ls1 += __shfl_xor_sync(0xffffffffu, ls1, 1);
        ls1 += __shfl_xor_sync(0xffffffffu, ls1, 2);
        l0 = l0*c0 + ls0;  l1 = l1*c1 + ls1;
#pragma unroll
        for (int j=0;j<8;j++){
            o[j][0]*=c0; o[j][1]*=c0; o[j][2]*=c1; o[j][3]*=c1;
        }
        __syncwarp();

#pragma unroll
        for (int kk=0; kk<8; kk++){
            const int ko = kk*8 + t;
            unsigned a0 = *(const unsigned*)&sP[arow0 + ko];
            unsigned a1 = *(const unsigned*)&sP[arow1 + ko];
            unsigned a2 = *(const unsigned*)&sP[arow0 + ko + 4];
            unsigned a3 = *(const unsigned*)&sP[arow1 + ko + 4];
#pragma unroll
            for (int j=0;j<8;j++){
                unsigned b0 = *(const unsigned*)&sV[ko*VS + 8*j + g];
                unsigned b1 = *(const unsigned*)&sV[(ko+4)*VS + 8*j + g];
                mma_tf32(o[j][0],o[j][1],o[j][2],o[j][3], a0,a1,a2,a3, b0,b1);
            }
        }
        __syncwarp();
    }

    float inv0 = __fdividef(1.0f, l0), inv1 = __fdividef(1.0f, l1);
    float* out0 = g_oc + ((size_t)(b*TT + bm + 16*w + g))*DD + h*HD;
    float* out1 = g_oc + ((size_t)(b*TT + bm + 16*w + g + 8))*DD + h*HD;
#pragma unroll
    for (int j=0;j<8;j++){
        int cb = 8*j + 2*t;
        float2 v0 = {o[j][0]*inv0, o[j][1]*inv0};
        float2 v1 = {o[j][2]*inv1, o[j][3]*inv1};
        *(float2*)(out0 + cb) = v0;
        *(float2*)(out1 + cb) = v1;
    }
}

// ---------------- xproj: per (b,t), 16 dots of o-row with folded weights ----
__global__ void xproj_kernel()
{
    __shared__ float sW[16][256];
    __shared__ float sBT[16];
    const int tid = threadIdx.x;
    for (int i=tid; i<16*256; i+=256)
        sW[i>>8][i&255] = g_Wc[i];
    if (tid < 16) sBT[tid] = g_bc[tid];
    __syncthreads();
    const int m = blockIdx.x*8 + (tid>>5);    // row over (b,t)
    const int lane = tid & 31;
    const float* arow = g_oc + (size_t)m*256;
    float av[8];
#pragma unroll
    for (int q=0;q<8;q++) av[q] = arow[lane + 32*q];
    float myval = 0.f;
#pragma unroll
    for (int r=0; r<16; r++){
        float acc = 0.f;
#pragma unroll
        for (int q=0;q<8;q++) acc += av[q]*sW[r][lane + 32*q];
#pragma unroll
        for (int off=16; off; off>>=1) acc += __shfl_xor_sync(0xffffffffu, acc, off);
        if (lane == r) myval = acc;
    }
    if (lane < 16){
        int b = m>>9, t = m&511;
        g_xp[((size_t)t*BB + b)*16 + lane] = myval + sBT[lane];
    }
}

// ---------------- sequential LSTM scan: 4 lanes per batch, no barriers -------
// Quantum layer closed form: <Z0>=C1C2C3, <Z1>=C0C1, <Z2>=C0C1C2, <Z3>=C0C1C2C3
// Gate activation args are cosine products => |z|<=1: poly activations (FMA pipe).
__global__ void lstm_kernel(const float* __restrict__ Wf, const float* __restrict__ Wi,
                            const float* __restrict__ Wg, const float* __restrict__ Wo2)
{
    const int lane = threadIdx.x;
    const int gate = lane & 3;
    const int bat  = blockIdx.x*8 + (lane>>2);
    const float* Wsel = (gate==0)?Wf:(gate==1)?Wi:(gate==2)?Wg:Wo2;
    float wh[4][4];
#pragma unroll
    for (int j=0;j<4;j++)
#pragma unroll
        for (int m2=0;m2<4;m2++)
            wh[j][m2] = Wsel[j*260 + 256 + m2];
    const bool isg = (gate==2);
    float cx0=0,cx1=0,cx2=0,cx3=0;
    float hx0=0,hx1=0,hx2=0,hx3=0;
    const float4* xpp = (const float4*)g_xp;
    float4 cur = xpp[(size_t)bat*4 + gate];
    const int gb = lane & ~3;
    for (int t=0; t<TT; t++){
        float4 nxt = cur;
        if (t+1 < TT) nxt = xpp[((size_t)(t+1)*BB + bat)*4 + gate];
        float a0 = cur.x + hx0*wh[0][0]+hx1*wh[0][1]+hx2*wh[0][2]+hx3*wh[0][3];
        float a1 = cur.y + hx0*wh[1][0]+hx1*wh[1][1]+hx2*wh[1][2]+hx3*wh[1][3];
        float a2 = cur.z + hx0*wh[2][0]+hx1*wh[2][1]+hx2*wh[2][2]+hx3*wh[2][3];
        float a3 = cur.w + hx0*wh[3][0]+hx1*wh[3][1]+hx2*wh[3][2]+hx3*wh[3][3];
        float C0=__cosf(a0), C1=__cosf(a1), C2=__cosf(a2), C3=__cosf(a3);
        float t12 = C1*C2;
        float z0 = t12*C3, z1 = C0*C1, z2 = C0*t12, z3 = z2*C3;
        float v0,v1,v2,v3;
        if (isg){ v0=tanh1(z0); v1=tanh1(z1); v2=tanh1(z2); v3=tanh1(z3); }
        else    { v0=sigd1(z0); v1=sigd1(z1); v2=sigd1(z2); v3=sigd1(z3); }
        float f0=__shfl_sync(0xffffffffu,v0,gb+0), i0=__shfl_sync(0xffffffffu,v0,gb+1),
              q0=__shfl_sync(0xffffffffu,v0,gb+2), o0=__shfl_sync(0xffffffffu,v0,gb+3);
        float f1=__shfl_sync(0xffffffffu,v1,gb+0), i1=__shfl_sync(0xffffffffu,v1,gb+1),
              q1=__shfl_sync(0xffffffffu,v1,gb+2), o1=__shfl_sync(0xffffffffu,v1,gb+3);
        float f2=__shfl_sync(0xffffffffu,v2,gb+0), i2=__shfl_sync(0xffffffffu,v2,gb+1),
              q2=__shfl_sync(0xffffffffu,v2,gb+2), o2=__shfl_sync(0xffffffffu,v2,gb+3);
        float f3=__shfl_sync(0xffffffffu,v3,gb+0), i3=__shfl_sync(0xffffffffu,v3,gb+1),
              q3=__shfl_sync(0xffffffffu,v3,gb+2), o3=__shfl_sync(0xffffffffu,v3,gb+3);
        cx0 = f0*cx0 + i0*q0;  hx0 = o0*ftanh(cx0);
        cx1 = f1*cx1 + i1*q1;  hx1 = o1*ftanh(cx1);
        cx2 = f2*cx2 + i2*q2;  hx2 = o2*ftanh(cx2);
        cx3 = f3*cx3 + i3*q3;  hx3 = o3*ftanh(cx3);
        float outv = (gate==0)?hx0:(gate==1)?hx1:(gate==2)?hx2:hx3;
        g_hs[((size_t)bat*TT + t)*4 + gate] = outv;
        cur = nxt;
    }
}

// ---------------- logits + log_softmax: one warp per (b,t) -------------------
__global__ void logits_kernel(const float* __restrict__ Wt,
                              const float* __restrict__ bt,
                              float* __restrict__ out)
{
    const int w = (blockIdx.x*blockDim.x + threadIdx.x) >> 5;   // 0..8191
    const int lane = threadIdx.x & 31;
    float4 h = *(const float4*)(g_hs + (size_t)w*4);
    int j0 = lane, j1 = lane + 32;
    float l0 = bt[j0] + h.x*Wt[j0*4+0] + h.y*Wt[j0*4+1] + h.z*Wt[j0*4+2] + h.w*Wt[j0*4+3];
    float l1 = bt[j1] + h.x*Wt[j1*4+0] + h.y*Wt[j1*4+1] + h.z*Wt[j1*4+2] + h.w*Wt[j1*4+3];
    float m = fmaxf(l0, l1);
#pragma unroll
    for (int off=16; off; off>>=1) m = fmaxf(m, __shfl_xor_sync(0xffffffffu, m, off));
    float s = __expf(l0-m) + __expf(l1-m);
#pragma unroll
    for (int off=16; off; off>>=1) s += __shfl_xor_sync(0xffffffffu, s, off);
    float ls = __logf(s) + m;
    out[(size_t)w*64 + j0] = l0 - ls;
    out[(size_t)w*64 + j1] = l1 - ls;
}

// ---------------- launch ------------------------------------------------------
extern "C" void kernel_launch(void* const* d_in, const int* in_sizes, int n_in,
                              void* d_out, int out_size)
{
    (void)in_sizes; (void)n_in; (void)out_size;
    const int*   sentence = (const int*)  d_in[0];
    const float* emb = (const float*)d_in[1];
    const float* Wq  = (const float*)d_in[2];  const float* bq  = (const float*)d_in[3];
    const float* Wk  = (const float*)d_in[4];  const float* bk  = (const float*)d_in[5];
    const float* Wv  = (const float*)d_in[6];  const float* bv  = (const float*)d_in[7];
    const float* Wo  = (const float*)d_in[8];  const float* bo  = (const float*)d_in[9];
    const float* Wf  = (const float*)d_in[10]; const float* bf  = (const float*)d_in[11];
    const float* thf = (const float*)d_in[12];
    const float* Wi  = (const float*)d_in[13]; const float* bi  = (const float*)d_in[14];
    const float* thi = (const float*)d_in[15];
    const float* Wg  = (const float*)d_in[16]; const float* bg  = (const float*)d_in[17];
    const float* thg = (const float*)d_in[18];
    const float* Wo2 = (const float*)d_in[19]; const float* bo2 = (const float*)d_in[20];
    const float* tho = (const float*)d_in[21];
    const float* Wt  = (const float*)d_in[22]; const float* bt  = (const float*)d_in[23];
    float* out = (float*)d_out;

    static bool attr_done = false;
    if (!attr_done){
        cudaFuncSetAttribute(flash_kernel,
                             cudaFuncAttributeMaxDynamicSharedMemorySize, FLASH_SMEM);
        attr_done = true;
    }

    // fold Wo into gate weights (tiny, runs while nothing else is pending)
    wc_kernel<<<16, 256>>>(Wf, Wi, Wg, Wo2, Wo, bo,
                           bf, thf, bi, thi, bg, thg, bo2, tho);
    // QKV on tensor cores
    proj_mma_kernel<<<dim3(64, 4, 3), 256>>>(emb, sentence, Wq, bq, Wk, bk, Wv, bv);
    // fused attention (scores + softmax + PV) on tensor cores
    flash_kernel<<<dim3(4, 64), 256, FLASH_SMEM>>>();
    // gate pre-activations straight from attention output (oproj folded away)
    xproj_kernel<<<1024, 256>>>();
    lstm_kernel<<<2, 32>>>(Wf, Wi, Wg, Wo2);
    logits_kernel<<<1024, 256>>>(Wt, bt, out);
}

// round 17
// speedup vs baseline: 1.0463x; 1.0463x over previous
#include <cuda_runtime.h>
#include <cstddef>

#define BB 16
#define TT 512
#define DD 256
#define HH 4
#define HD 64
#define MM (BB*TT)          // 8192

// ---------------- scratch (static device memory; no allocs) ----------------
__device__ float g_q[MM*DD];
__device__ float g_k[MM*DD];
__device__ float g_v[MM*DD];
__device__ float g_oc[MM*DD];
__device__ float g_xp[TT*BB*16];             // per-step gate pre-activations
__device__ float g_hs[BB*TT*4];              // lstm hidden outputs
__device__ float g_Wc[16*256];               // folded gate@Wo weights
__device__ float g_bc[16];                   // folded bias (Wg.bo + b + theta)

__device__ __forceinline__ float ftanh(float x){
    float e = __expf(2.0f*x);
    return __fdividef(e - 1.0f, e + 1.0f);
}
// sigmoid for |z| <= 1 (Taylor-9, max err ~2e-6 at |z|=1), FMA-pipe only
__device__ __forceinline__ float sigd1(float z){
    float u = z*z;
    float p = -17.f/80640.f + u*(31.f/1451520.f);
    p = 1.f/480.f + u*p;
    p = -1.f/48.f + u*p;
    p = 0.25f + u*p;
    return 0.5f + z*p;
}
// tanh for |z| <= 1 (Pade(5,4) of continued fraction, max err ~5e-8)
__device__ __forceinline__ float tanh1(float z){
    float u = z*z;
    float num = 945.f + u*(105.f + u);
    float den = 945.f + u*(420.f + 15.f*u);
    return z*__fdividef(num, den);
}

__device__ __forceinline__ unsigned tf32u(float x){
    unsigned y; asm("cvt.rna.tf32.f32 %0, %1;" : "=r"(y) : "f"(x)); return y;
}
__device__ __forceinline__ float tf32f(float x){
    return __uint_as_float(tf32u(x));
}
__device__ __forceinline__ void mma_tf32(float&c0,float&c1,float&c2,float&c3,
    unsigned a0,unsigned a1,unsigned a2,unsigned a3,unsigned b0,unsigned b1){
    asm("mma.sync.aligned.m16n8k8.row.col.f32.tf32.tf32.f32 "
        "{%0,%1,%2,%3},{%4,%5,%6,%7},{%8,%9},{%0,%1,%2,%3};"
        : "+f"(c0),"+f"(c1),"+f"(c2),"+f"(c3)
        : "r"(a0),"r"(a1),"r"(a2),"r"(a3),"r"(b0),"r"(b1));
}

// ============================================================================
// Fold Wo into the gate weights: Wc[r][k] = sum_c Wgate_r[c] * Wo[c][k],
// bc[r] = sum_c Wgate_r[c]*bo[c] + b_r + theta_r.   Grid = 16 blocks (one per
// gate-row r), 256 threads (one per k). 8 accumulators + full unroll keep
// ~32 loads in flight (latency-bound otherwise: this kernel is stream-serial).
// ============================================================================
__global__ void wc_kernel(const float* __restrict__ Wf, const float* __restrict__ Wi,
                          const float* __restrict__ Wg, const float* __restrict__ Wo2,
                          const float* __restrict__ Wo, const float* __restrict__ bo,
                          const float* __restrict__ bf, const float* __restrict__ thf,
                          const float* __restrict__ bi, const float* __restrict__ thi,
                          const float* __restrict__ bg, const float* __restrict__ thg,
                          const float* __restrict__ bo2, const float* __restrict__ tho)
{
    __shared__ float sG[256];
    __shared__ float red[256];
    const int r = blockIdx.x;                 // 0..15
    const float* Wgate = (r<4)?Wf:(r<8)?Wi:(r<12)?Wg:Wo2;
    const float* bias  = (r<4)?bf:(r<8)?bi:(r<12)?bg:bo2;
    const float* th    = (r<4)?thf:(r<8)?thi:(r<12)?thg:tho;
    const int rr = r & 3;
    const int k = threadIdx.x;
    sG[k] = Wgate[rr*260 + k];
    __syncthreads();
    float a0=0.f,a1=0.f,a2=0.f,a3=0.f,a4=0.f,a5=0.f,a6=0.f,a7=0.f;
#pragma unroll
    for (int c=0; c<256; c+=8){
        a0 += sG[c+0]*Wo[(size_t)(c+0)*256 + k];
        a1 += sG[c+1]*Wo[(size_t)(c+1)*256 + k];
        a2 += sG[c+2]*Wo[(size_t)(c+2)*256 + k];
        a3 += sG[c+3]*Wo[(size_t)(c+3)*256 + k];
        a4 += sG[c+4]*Wo[(size_t)(c+4)*256 + k];
        a5 += sG[c+5]*Wo[(size_t)(c+5)*256 + k];
        a6 += sG[c+6]*Wo[(size_t)(c+6)*256 + k];
        a7 += sG[c+7]*Wo[(size_t)(c+7)*256 + k];
    }
    g_Wc[r*256 + k] = ((a0+a1)+(a2+a3)) + ((a4+a5)+(a6+a7));
    red[k] = sG[k]*bo[k];
    __syncthreads();
    for (int s=128; s>0; s>>=1){
        if (k < s) red[k] += red[k+s];
        __syncthreads();
    }
    if (k == 0) g_bc[r] = red[0] + bias[rr] + th[rr];
}

// ============================================================================
// Projection GEMM on tensor cores (tf32 mma.sync m16n8k8), double-buffered.
// C[M=8192, N=256] = A[M,256] @ W[N,256]^T + bias.  A = emb[idx[.]] gather.
// One __syncthreads per k-chunk: iter kc does mma(buf), sts(buf^1), sync.
// buf^1 was last READ by mma in iter kc-1, which completed before iter
// kc-1's end-of-iter sync => write-after-read safe.
// ============================================================================
#define AS 36
#define WS 36

__global__ __launch_bounds__(256, 2)
void proj_mma_kernel(const float* __restrict__ emb,
                     const int*   __restrict__ idx,
                     const float* __restrict__ Wq, const float* __restrict__ bq,
                     const float* __restrict__ Wk, const float* __restrict__ bk,
                     const float* __restrict__ Wv, const float* __restrict__ bv)
{
    __shared__ float sA[2][128*AS];
    __shared__ float sW[2][64*WS];
    const int sel = blockIdx.z;
    const float* Wm   = (sel==0)?Wq:(sel==1)?Wk:Wv;
    const float* bias = (sel==0)?bq:(sel==1)?bk:bv;
    float* C          = (sel==0)?g_q:(sel==1)?g_k:g_v;
    const int tid = threadIdx.x;
    const int bm = blockIdx.x*128, bn = blockIdx.y*64;
    const int w = tid>>5, lane = tid&31;
    const int g = lane>>2, t = lane&3;

    const int ar = tid>>1, ac0 = (tid&1)*16;        // A: row, 16 cols
    const int wr = tid>>2, wc0 = (tid&3)*8;         // W: row, 8 cols
    const float* arow = emb + (size_t)idx[bm+ar]*DD + ac0;
    const float* brow = Wm + (size_t)(bn+wr)*DD + wc0;

    float s[8][4] = {};
    const int qrow0 = (16*w + g)*AS;
    const int qrow1 = (16*w + g + 8)*AS;

    // prefetch chunk 0
    float4 pa0 = *(const float4*)(arow + 0);
    float4 pa1 = *(const float4*)(arow + 4);
    float4 pa2 = *(const float4*)(arow + 8);
    float4 pa3 = *(const float4*)(arow + 12);
    float4 pw0 = *(const float4*)(brow + 0);
    float4 pw1 = *(const float4*)(brow + 4);
    {
        float* a = &sA[0][ar*AS + ac0];
        a[0]=tf32f(pa0.x); a[1]=tf32f(pa0.y); a[2]=tf32f(pa0.z); a[3]=tf32f(pa0.w);
        a[4]=tf32f(pa1.x); a[5]=tf32f(pa1.y); a[6]=tf32f(pa1.z); a[7]=tf32f(pa1.w);
        a[8]=tf32f(pa2.x); a[9]=tf32f(pa2.y); a[10]=tf32f(pa2.z); a[11]=tf32f(pa2.w);
        a[12]=tf32f(pa3.x); a[13]=tf32f(pa3.y); a[14]=tf32f(pa3.z); a[15]=tf32f(pa3.w);
        float* b = &sW[0][wr*WS + wc0];
        b[0]=tf32f(pw0.x); b[1]=tf32f(pw0.y); b[2]=tf32f(pw0.z); b[3]=tf32f(pw0.w);
        b[4]=tf32f(pw1.x); b[5]=tf32f(pw1.y); b[6]=tf32f(pw1.z); b[7]=tf32f(pw1.w);
    }
    __syncthreads();

#pragma unroll 1
    for (int kc=0; kc<8; kc++){
        const int buf = kc & 1;
        if (kc < 7){
            pa0 = *(const float4*)(arow + (kc+1)*32 + 0);
            pa1 = *(const float4*)(arow + (kc+1)*32 + 4);
            pa2 = *(const float4*)(arow + (kc+1)*32 + 8);
            pa3 = *(const float4*)(arow + (kc+1)*32 + 12);
            pw0 = *(const float4*)(brow + (kc+1)*32 + 0);
            pw1 = *(const float4*)(brow + (kc+1)*32 + 4);
        }
#pragma unroll
        for (int kk=0; kk<4; kk++){
            const int ko = kk*8 + t;
            unsigned a0 = *(const unsigned*)&sA[buf][qrow0 + ko];
            unsigned a1 = *(const unsigned*)&sA[buf][qrow1 + ko];
            unsigned a2 = *(const unsigned*)&sA[buf][qrow0 + ko + 4];
            unsigned a3 = *(const unsigned*)&sA[buf][qrow1 + ko + 4];
#pragma unroll
            for (int j=0;j<8;j++){
                unsigned b0 = *(const unsigned*)&sW[buf][(8*j+g)*WS + ko];
                unsigned b1 = *(const unsigned*)&sW[buf][(8*j+g)*WS + ko + 4];
                mma_tf32(s[j][0],s[j][1],s[j][2],s[j][3], a0,a1,a2,a3, b0,b1);
            }
        }
        if (kc < 7){
            float* a = &sA[buf^1][ar*AS + ac0];
            a[0]=tf32f(pa0.x); a[1]=tf32f(pa0.y); a[2]=tf32f(pa0.z); a[3]=tf32f(pa0.w);
            a[4]=tf32f(pa1.x); a[5]=tf32f(pa1.y); a[6]=tf32f(pa1.z); a[7]=tf32f(pa1.w);
            a[8]=tf32f(pa2.x); a[9]=tf32f(pa2.y); a[10]=tf32f(pa2.z); a[11]=tf32f(pa2.w);
            a[12]=tf32f(pa3.x); a[13]=tf32f(pa3.y); a[14]=tf32f(pa3.z); a[15]=tf32f(pa3.w);
            float* b = &sW[buf^1][wr*WS + wc0];
            b[0]=tf32f(pw0.x); b[1]=tf32f(pw0.y); b[2]=tf32f(pw0.z); b[3]=tf32f(pw0.w);
            b[4]=tf32f(pw1.x); b[5]=tf32f(pw1.y); b[6]=tf32f(pw1.z); b[7]=tf32f(pw1.w);
            __syncthreads();
        }
    }

    float* out0 = C + (size_t)(bm + 16*w + g)*DD + bn;
    float* out1 = C + (size_t)(bm + 16*w + g + 8)*DD + bn;
#pragma unroll
    for (int j=0;j<8;j++){
        int cb = 8*j + 2*t;
        float b0 = bias[bn + cb], b1 = bias[bn + cb + 1];
        float2 v0 = {s[j][0]+b0, s[j][1]+b1};
        float2 v1 = {s[j][2]+b0, s[j][3]+b1};
        *(float2*)(out0 + cb) = v0;
        *(float2*)(out1 + cb) = v1;
    }
}

// ============================================================================
// Fused flash attention on tensor cores (tf32 mma.sync m16n8k8).
// grid (4 m-chunks of 128 rows, 64 bh), 256 threads = 8 warps.
// ============================================================================
#define QS 68
#define KS 68
#define VS 72
#define PS 68
#define FLASH_SMEM ((128*QS + 64*KS + 64*VS + 128*PS)*4)

__global__ __launch_bounds__(256, 2)
void flash_kernel()
{
    extern __shared__ float sm[];
    float* sQ = sm;                 // [128][QS] tf32
    float* sK = sQ + 128*QS;        // [64][KS]  tf32 (n-major: sK[n][k])
    float* sV = sK + 64*KS;         // [64][VS]  tf32 (kv-major: sV[kv][d])
    float* sP = sV + 64*VS;         // [128][PS] tf32

    const int bh = blockIdx.y, b = bh>>2, h = bh&3;
    const int bm = blockIdx.x*128;
    const int tid = threadIdx.x;
    const int w = tid>>5, lane = tid&31;
    const int g = lane>>2, t = lane&3;

    {
        int r = tid>>1, d0 = (tid&1)*32;
        const float* src = g_q + ((size_t)(b*TT + bm + r))*DD + h*HD + d0;
#pragma unroll
        for (int j=0;j<32;j+=4){
            float4 v = *(const float4*)(src + j);
            sQ[r*QS + d0 + j + 0] = tf32f(v.x);
            sQ[r*QS + d0 + j + 1] = tf32f(v.y);
            sQ[r*QS + d0 + j + 2] = tf32f(v.z);
            sQ[r*QS + d0 + j + 3] = tf32f(v.w);
        }
    }

    float o[8][4] = {};
    float m0=-1e30f, m1=-1e30f, l0=0.f, l1=0.f;

    const int arow0 = (16*w + g)*PS;
    const int arow1 = (16*w + g + 8)*PS;
    const int qrow0 = (16*w + g)*QS;
    const int qrow1 = (16*w + g + 8)*QS;

    for (int n0=0; n0<TT; n0+=64){
        __syncthreads();
        {
            int n = tid>>2, d0 = (tid&3)*16;
            const float* ksrc = g_k + ((size_t)(b*TT + n0 + n))*DD + h*HD + d0;
            const float* vsrc = g_v + ((size_t)(b*TT + n0 + n))*DD + h*HD + d0;
#pragma unroll
            for (int j=0;j<16;j+=4){
                float4 kv4 = *(const float4*)(ksrc + j);
                float4 vv4 = *(const float4*)(vsrc + j);
                sK[n*KS + d0 + j + 0] = tf32f(kv4.x);
                sK[n*KS + d0 + j + 1] = tf32f(kv4.y);
                sK[n*KS + d0 + j + 2] = tf32f(kv4.z);
                sK[n*KS + d0 + j + 3] = tf32f(kv4.w);
                sV[n*VS + d0 + j + 0] = tf32f(vv4.x);
                sV[n*VS + d0 + j + 1] = tf32f(vv4.y);
                sV[n*VS + d0 + j + 2] = tf32f(vv4.z);
                sV[n*VS + d0 + j + 3] = tf32f(vv4.w);
            }
        }
        __syncthreads();

        float s[8][4] = {};
#pragma unroll
        for (int kk=0; kk<8; kk++){
            const int ko = kk*8 + t;
            unsigned a0 = *(const unsigned*)&sQ[qrow0 + ko];
            unsigned a1 = *(const unsigned*)&sQ[qrow1 + ko];
            unsigned a2 = *(const unsigned*)&sQ[qrow0 + ko + 4];
            unsigned a3 = *(const unsigned*)&sQ[qrow1 + ko + 4];
#pragma unroll
            for (int j=0;j<8;j++){
                unsigned b0 = *(const unsigned*)&sK[(8*j+g)*KS + ko];
                unsigned b1 = *(const unsigned*)&sK[(8*j+g)*KS + ko + 4];
                mma_tf32(s[j][0],s[j][1],s[j][2],s[j][3], a0,a1,a2,a3, b0,b1);
            }
        }

        float lm0=-1e30f, lm1=-1e30f;
#pragma unroll
        for (int j=0;j<8;j++){
            s[j][0]*=0.125f; s[j][1]*=0.125f; s[j][2]*=0.125f; s[j][3]*=0.125f;
            lm0 = fmaxf(lm0, fmaxf(s[j][0], s[j][1]));
            lm1 = fmaxf(lm1, fmaxf(s[j][2], s[j][3]));
        }
        lm0 = fmaxf(lm0, __shfl_xor_sync(0xffffffffu, lm0, 1));
        lm0 = fmaxf(lm0, __shfl_xor_sync(0xffffffffu, lm0, 2));
        lm1 = fmaxf(lm1, __shfl_xor_sync(0xffffffffu, lm1, 1));
        lm1 = fmaxf(lm1, __shfl_xor_sync(0xffffffffu, lm1, 2));
        float nm0 = fmaxf(m0, lm0), nm1 = fmaxf(m1, lm1);
        float c0 = __expf(m0 - nm0), c1 = __expf(m1 - nm1);
        m0 = nm0; m1 = nm1;
        float ls0 = 0.f, ls1 = 0.f;
#pragma unroll
        for (int j=0;j<8;j++){
            float p00 = __expf(s[j][0]-nm0), p01 = __expf(s[j][1]-nm0);
            float p10 = __expf(s[j][2]-nm1), p11 = __expf(s[j][3]-nm1);
            ls0 += p00 + p01;  ls1 += p10 + p11;
            int cb = 8*j + 2*t;
            sP[arow0 + cb]     = tf32f(p00);
            sP[arow0 + cb + 1] = tf32f(p01);
            sP[arow1 + cb]     = tf32f(p10);
            sP[arow1 + cb + 1] = tf32f(p11);
        }
        ls0 += __shfl_xor_sync(0xffffffffu, ls0, 1);
        ls0 += __shfl_xor_sync(0xffffffffu, ls0, 2);
        ls1 += __shfl_xor_sync(0xffffffffu, ls1, 1);
        ls1 += __shfl_xor_sync(0xffffffffu, ls1, 2);
        l0 = l0*c0 + ls0;  l1 = l1*c1 + ls1;
#pragma unroll
        for (int j=0;j<8;j++){
            o[j][0]*=c0; o[j][1]*=c0; o[j][2]*=c1; o[j][3]*=c1;
        }
        __syncwarp();

#pragma unroll
        for (int kk=0; kk<8; kk++){
            const int ko = kk*8 + t;
            unsigned a0 = *(const unsigned*)&sP[arow0 + ko];
            unsigned a1 = *(const unsigned*)&sP[arow1 + ko];
            unsigned a2 = *(const unsigned*)&sP[arow0 + ko + 4];
            unsigned a3 = *(const unsigned*)&sP[arow1 + ko + 4];
#pragma unroll
            for (int j=0;j<8;j++){
                unsigned b0 = *(const unsigned*)&sV[ko*VS + 8*j + g];
                unsigned b1 = *(const unsigned*)&sV[(ko+4)*VS + 8*j + g];
                mma_tf32(o[j][0],o[j][1],o[j][2],o[j][3], a0,a1,a2,a3, b0,b1);
            }
        }
        __syncwarp();
    }

    float inv0 = __fdividef(1.0f, l0), inv1 = __fdividef(1.0f, l1);
    float* out0 = g_oc + ((size_t)(b*TT + bm + 16*w + g))*DD + h*HD;
    float* out1 = g_oc + ((size_t)(b*TT + bm + 16*w + g + 8))*DD + h*HD;
#pragma unroll
    for (int j=0;j<8;j++){
        int cb = 8*j + 2*t;
        float2 v0 = {o[j][0]*inv0, o[j][1]*inv0};
        float2 v1 = {o[j][2]*inv1, o[j][3]*inv1};
        *(float2*)(out0 + cb) = v0;
        *(float2*)(out1 + cb) = v1;
    }
}

// ---------------- xproj: per (b,t), 16 dots of o-row with folded weights ----
__global__ void xproj_kernel()
{
    __shared__ float sW[16][256];
    __shared__ float sBT[16];
    const int tid = threadIdx.x;
    for (int i=tid; i<16*256; i+=256)
        sW[i>>8][i&255] = g_Wc[i];
    if (tid < 16) sBT[tid] = g_bc[tid];
    __syncthreads();
    const int m = blockIdx.x*8 + (tid>>5);    // row over (b,t)
    const int lane = tid & 31;
    const float* arow = g_oc + (size_t)m*256;
    float av[8];
#pragma unroll
    for (int q=0;q<8;q++) av[q] = arow[lane + 32*q];
    float myval = 0.f;
#pragma unroll
    for (int r=0; r<16; r++){
        float acc = 0.f;
#pragma unroll
        for (int q=0;q<8;q++) acc += av[q]*sW[r][lane + 32*q];
#pragma unroll
        for (int off=16; off; off>>=1) acc += __shfl_xor_sync(0xffffffffu, acc, off);
        if (lane == r) myval = acc;
    }
    if (lane < 16){
        int b = m>>9, t = m&511;
        g_xp[((size_t)t*BB + b)*16 + lane] = myval + sBT[lane];
    }
}

// ---------------- sequential LSTM scan: 4 lanes per batch, no barriers -------
// Quantum layer closed form: <Z0>=C1C2C3, <Z1>=C0C1, <Z2>=C0C1C2, <Z3>=C0C1C2C3
// Gate activation args are cosine products => |z|<=1: poly activations (FMA pipe).
__global__ void lstm_kernel(const float* __restrict__ Wf, const float* __restrict__ Wi,
                            const float* __restrict__ Wg, const float* __restrict__ Wo2)
{
    const int lane = threadIdx.x;
    const int gate = lane & 3;
    const int bat  = blockIdx.x*8 + (lane>>2);
    const float* Wsel = (gate==0)?Wf:(gate==1)?Wi:(gate==2)?Wg:Wo2;
    float wh[4][4];
#pragma unroll
    for (int j=0;j<4;j++)
#pragma unroll
        for (int m2=0;m2<4;m2++)
            wh[j][m2] = Wsel[j*260 + 256 + m2];
    const bool isg = (gate==2);
    float cx0=0,cx1=0,cx2=0,cx3=0;
    float hx0=0,hx1=0,hx2=0,hx3=0;
    const float4* xpp = (const float4*)g_xp;
    float4 cur = xpp[(size_t)bat*4 + gate];
    const int gb = lane & ~3;
    for (int t=0; t<TT; t++){
        float4 nxt = cur;
        if (t+1 < TT) nxt = xpp[((size_t)(t+1)*BB + bat)*4 + gate];
        float a0 = cur.x + hx0*wh[0][0]+hx1*wh[0][1]+hx2*wh[0][2]+hx3*wh[0][3];
        float a1 = cur.y + hx0*wh[1][0]+hx1*wh[1][1]+hx2*wh[1][2]+hx3*wh[1][3];
        float a2 = cur.z + hx0*wh[2][0]+hx1*wh[2][1]+hx2*wh[2][2]+hx3*wh[2][3];
        float a3 = cur.w + hx0*wh[3][0]+hx1*wh[3][1]+hx2*wh[3][2]+hx3*wh[3][3];
        float C0=__cosf(a0), C1=__cosf(a1), C2=__cosf(a2), C3=__cosf(a3);
        float t12 = C1*C2;
        float z0 = t12*C3, z1 = C0*C1, z2 = C0*t12, z3 = z2*C3;
        float v0,v1,v2,v3;
        if (isg){ v0=tanh1(z0); v1=tanh1(z1); v2=tanh1(z2); v3=tanh1(z3); }
        else    { v0=sigd1(z0); v1=sigd1(z1); v2=sigd1(z2); v3=sigd1(z3); }
        float f0=__shfl_sync(0xffffffffu,v0,gb+0), i0=__shfl_sync(0xffffffffu,v0,gb+1),
              q0=__shfl_sync(0xffffffffu,v0,gb+2), o0=__shfl_sync(0xffffffffu,v0,gb+3);
        float f1=__shfl_sync(0xffffffffu,v1,gb+0), i1=__shfl_sync(0xffffffffu,v1,gb+1),
              q1=__shfl_sync(0xffffffffu,v1,gb+2), o1=__shfl_sync(0xffffffffu,v1,gb+3);
        float f2=__shfl_sync(0xffffffffu,v2,gb+0), i2=__shfl_sync(0xffffffffu,v2,gb+1),
              q2=__shfl_sync(0xffffffffu,v2,gb+2), o2=__shfl_sync(0xffffffffu,v2,gb+3);
        float f3=__shfl_sync(0xffffffffu,v3,gb+0), i3=__shfl_sync(0xffffffffu,v3,gb+1),
              q3=__shfl_sync(0xffffffffu,v3,gb+2), o3=__shfl_sync(0xffffffffu,v3,gb+3);
        cx0 = f0*cx0 + i0*q0;  hx0 = o0*ftanh(cx0);
        cx1 = f1*cx1 + i1*q1;  hx1 = o1*ftanh(cx1);
        cx2 = f2*cx2 + i2*q2;  hx2 = o2*ftanh(cx2);
        cx3 = f3*cx3 + i3*q3;  hx3 = o3*ftanh(cx3);
        float outv = (gate==0)?hx0:(gate==1)?hx1:(gate==2)?hx2:hx3;
        g_hs[((size_t)bat*TT + t)*4 + gate] = outv;
        cur = nxt;
    }
}

// ---------------- logits + log_softmax: one warp per (b,t) -------------------
__global__ void logits_kernel(const float* __restrict__ Wt,
                              const float* __restrict__ bt,
                              float* __restrict__ out)
{
    const int w = (blockIdx.x*blockDim.x + threadIdx.x) >> 5;   // 0..8191
    const int lane = threadIdx.x & 31;
    float4 h = *(const float4*)(g_hs + (size_t)w*4);
    int j0 = lane, j1 = lane + 32;
    float l0 = bt[j0] + h.x*Wt[j0*4+0] + h.y*Wt[j0*4+1] + h.z*Wt[j0*4+2] + h.w*Wt[j0*4+3];
    float l1 = bt[j1] + h.x*Wt[j1*4+0] + h.y*Wt[j1*4+1] + h.z*Wt[j1*4+2] + h.w*Wt[j1*4+3];
    float m = fmaxf(l0, l1);
#pragma unroll
    for (int off=16; off; off>>=1) m = fmaxf(m, __shfl_xor_sync(0xffffffffu, m, off));
    float s = __expf(l0-m) + __expf(l1-m);
#pragma unroll
    for (int off=16; off; off>>=1) s += __shfl_xor_sync(0xffffffffu, s, off);
    float ls = __logf(s) + m;
    out[(size_t)w*64 + j0] = l0 - ls;
    out[(size_t)w*64 + j1] = l1 - ls;
}

// ---------------- launch ------------------------------------------------------
extern "C" void kernel_launch(void* const* d_in, const int* in_sizes, int n_in,
                              void* d_out, int out_size)
{
    (void)in_sizes; (void)n_in; (void)out_size;
    const int*   sentence = (const int*)  d_in[0];
    const float* emb = (const float*)d_in[1];
    const float* Wq  = (const float*)d_in[2];  const float* bq  = (const float*)d_in[3];
    const float* Wk  = (const float*)d_in[4];  const float* bk  = (const float*)d_in[5];
    const float* Wv  = (const float*)d_in[6];  const float* bv  = (const float*)d_in[7];
    const float* Wo  = (const float*)d_in[8];  const float* bo  = (const float*)d_in[9];
    const float* Wf  = (const float*)d_in[10]; const float* bf  = (const float*)d_in[11];
    const float* thf = (const float*)d_in[12];
    const float* Wi  = (const float*)d_in[13]; const float* bi  = (const float*)d_in[14];
    const float* thi = (const float*)d_in[15];
    const float* Wg  = (const float*)d_in[16]; const float* bg  = (const float*)d_in[17];
    const float* thg = (const float*)d_in[18];
    const float* Wo2 = (const float*)d_in[19]; const float* bo2 = (const float*)d_in[20];
    const float* tho = (const float*)d_in[21];
    const float* Wt  = (const float*)d_in[22]; const float* bt  = (const float*)d_in[23];
    float* out = (float*)d_out;

    static bool attr_done = false;
    if (!attr_done){
        cudaFuncSetAttribute(flash_kernel,
                             cudaFuncAttributeMaxDynamicSharedMemorySize, FLASH_SMEM);
        attr_done = true;
    }

    // fold Wo into gate weights (now MLP-optimized, ~4-5us)
    wc_kernel<<<16, 256>>>(Wf, Wi, Wg, Wo2, Wo, bo,
                           bf, thf, bi, thi, bg, thg, bo2, tho);
    // QKV on tensor cores, double-buffered
    proj_mma_kernel<<<dim3(64, 4, 3), 256>>>(emb, sentence, Wq, bq, Wk, bk, Wv, bv);
    // fused attention (scores + softmax + PV) on tensor cores
    flash_kernel<<<dim3(4, 64), 256, FLASH_SMEM>>>();
    // gate pre-activations straight from attention output (oproj folded away)
    xproj_kernel<<<1024, 256>>>();
    lstm_kernel<<<2, 32>>>(Wf, Wi, Wg, Wo2);
    logits_kernel<<<1024, 256>>>(Wt, bt, out);
}